// round 13
// baseline (speedup 1.0000x reference)
#include <cuda_runtime.h>
#include <cuda_fp16.h>
#include <cstdint>

// ============================================================================
// CoCov via mma.sync (HMMA) fp16 single-pass, input-shift formulation.
// out[p] = sum_{kt 3x3} sum_{tap 3x3} X_kt[p + (dh-1,dw-1)] @ W[kt,tap]
// B in mma-fragment order in DRAM, per-warp __ldg with k16 register ping-pong
// (L1-resident). A pre-converted to swizzled fp16 panels (preproc kernel also
// rearranges W), cp.async double-buffered, ONE barrier per kt. Warp-uniform
// zero-fragment skip on shifted-out pixel rows.
// ============================================================================

// B in fragment order: [T=kt*9+tap][k16 4][nt 8][lane 32] uint2
__device__ uint2 g_bw2[81 * 1024];
// pre-converted A panels: [b*256 + u1*16 + u2][pix 256][128B swizzled row]
__device__ uint4 g_bA[2048 * 2048];

// one preprocessing kernel: every block does its A panel; first 324 blocks
// additionally rearrange the weights (81*1024 uint2 elements).
__global__ void __launch_bounds__(256) prep_kernel(const float* __restrict__ inp,
                                                   const float* __restrict__ K) {
    extern __shared__ char sm[];
    const int tid = threadIdx.x;
    const int u2 = blockIdx.x, u1 = blockIdx.y, b = blockIdx.z;
    const int bid = (b * 16 + u1) * 16 + u2;

    // ---- weight rearrange (blocks 0..323) ----
    {
        int gid = bid * 256 + tid;
        if (gid < 81 * 1024) {
            int lane = gid & 31;
            int nt   = (gid >> 5) & 7;
            int k16  = (gid >> 8) & 3;
            int T    = gid >> 10;
            int tp = T % 9, kt = T / 9;
            int co = nt * 8 + (lane >> 2);
            int k0 = k16 * 16 + (lane & 3) * 2;
            const float* Kc = K + ((kt * 64 + co) * 64) * 9 + tp;   // [k][co][ci][dh][dw]
            __half2 lo2(__float2half(Kc[(size_t)k0 * 9]),
                        __float2half(Kc[(size_t)(k0 + 1) * 9]));
            __half2 hi2(__float2half(Kc[(size_t)(k0 + 8) * 9]),
                        __float2half(Kc[(size_t)(k0 + 9) * 9]));
            g_bw2[gid] = make_uint2(*(uint32_t*)&lo2, *(uint32_t*)&hi2);
        }
    }

    // ---- A panel convert: fp32 -> fp16, swizzled 128B rows ----
    const float* src = inp + (size_t)b * 64 * 65536
                     + (size_t)(u1 * 16 + (tid >> 4)) * 256 + u2 * 16 + (tid & 15);
    const uint32_t rowa = tid * 128;
    #pragma unroll
    for (int ch = 0; ch < 8; ch++) {
        uint32_t hi4[4];
        #pragma unroll
        for (int e = 0; e < 4; e++) {
            float x0 = __ldg(src + (size_t)(ch * 8 + 2 * e) * 65536);
            float x1 = __ldg(src + (size_t)(ch * 8 + 2 * e + 1) * 65536);
            __half2 hp(__float2half(x0), __float2half(x1));
            hi4[e] = *(uint32_t*)&hp;
        }
        uint32_t off = rowa + ((ch ^ (tid & 7)) << 4);
        *(uint4*)(sm + off) = make_uint4(hi4[0], hi4[1], hi4[2], hi4[3]);
    }
    __syncthreads();
    uint4* dst = g_bA + (size_t)bid * 2048;
    const uint4* s4 = (const uint4*)sm;
    #pragma unroll
    for (int k = 0; k < 8; k++) dst[tid + k * 256] = s4[tid + k * 256];
}

__device__ __forceinline__ uint32_t smem_u32(const void* p) {
    uint32_t a;
    asm("{ .reg .u64 t; cvta.to.shared.u64 t, %1; cvt.u32.u64 %0, t; }" : "=r"(a) : "l"(p));
    return a;
}
__device__ __forceinline__ void ldsm_x4(uint32_t* r, uint32_t addr) {
    asm volatile("ldmatrix.sync.aligned.m8n8.x4.shared.b16 {%0,%1,%2,%3}, [%4];"
                 : "=r"(r[0]), "=r"(r[1]), "=r"(r[2]), "=r"(r[3]) : "r"(addr));
}
__device__ __forceinline__ void mma16816(float* d, const uint32_t* a, const uint32_t* b) {
    asm volatile(
        "mma.sync.aligned.m16n8k16.row.col.f32.f16.f16.f32 "
        "{%0,%1,%2,%3}, {%4,%5,%6,%7}, {%8,%9}, {%0,%1,%2,%3};"
        : "+f"(d[0]), "+f"(d[1]), "+f"(d[2]), "+f"(d[3])
        : "r"(a[0]), "r"(a[1]), "r"(a[2]), "r"(a[3]), "r"(b[0]), "r"(b[1]));
}

#define CP16(dst, src, sz) \
    asm volatile("cp.async.cg.shared.global [%0], [%1], 16, %2;" \
                 :: "r"(dst), "l"(src), "r"(sz) : "memory")
#define CPCOMMIT() asm volatile("cp.async.commit_group;" ::: "memory")
#define CPWAIT0()  asm volatile("cp.async.wait_group 0;" ::: "memory")

// smem: A bufs: 2 x [257 rows][128B] (row 256 = zeros) = 65792,
// epilogue reuses smem as acc [pix 256][72] fp32 = 73728  -> SM_TOTAL = 73728
#define ABUF_SZ  32896              // 257 * 128
#define SM_TOTAL 73728              // max(2*ABUF_SZ, 256*72*4); 2 CTAs/SM

__global__ void __launch_bounds__(128, 2)
cocov_mma_kernel(float* __restrict__ out) {
    extern __shared__ char smem[];
    const uint32_t sb = smem_u32(smem);

    const int tid = threadIdx.x;
    const int lane = tid & 31;
    const int wid = tid >> 5;              // 0..3, each warp: 64 pixels
    const int t2 = blockIdx.x, t1 = blockIdx.y, b = blockIdx.z;
    const int M0 = wid * 64;

    // zero rows (row 256 of each A buf), written once (published by kt=0 barrier)
    if (tid < 64) {
        int buf = tid >> 5;
        *(float*)(smem + buf * ABUF_SZ + 256 * 128 + (tid & 31) * 4) = 0.f;
    }

    auto prefetch_A = [&](int kt) {
        const int tt1 = t1 + kt / 3 - 1;
        const int tt2 = t2 + kt % 3 - 1;
        const bool v = ((unsigned)tt1 < 16u) && ((unsigned)tt2 < 16u);
        const uint4* srcp = g_bA + (size_t)(b * 256 + (v ? tt1 * 16 + tt2 : 0)) * 2048;
        const int sz = v ? 16 : 0;
        const uint32_t abase = sb + (kt & 1) * ABUF_SZ;
        #pragma unroll
        for (int it = 0; it < 16; it++) {
            int e = tid + it * 128;            // 0..2047
            CP16(abase + e * 16, (const char*)(srcp + e), sz);
        }
    };

    // B fragment loader: tap T, k-step k16 -> 8 uint2 (one per nt)
    const uint2* bbase_g = g_bw2 + lane;
    auto load_bf = [&](int T, int k16, uint2* bf) {
        const uint2* p = bbase_g + (size_t)T * 1024 + k16 * 256;
        #pragma unroll
        for (int nt = 0; nt < 8; nt++) bf[nt] = __ldg(p + nt * 32);
    };

    // ldmatrix lane addressing pieces
    const int a_kc_lane = (lane >> 4);
    const int jlane     = lane & 15;

    float d[4][8][4];
    #pragma unroll
    for (int mt = 0; mt < 4; mt++)
        #pragma unroll
        for (int nt = 0; nt < 8; nt++)
            #pragma unroll
            for (int r = 0; r < 4; r++) d[mt][nt][r] = 0.f;

    uint2 bfA[8], bfB[8];

    // prologue
    prefetch_A(0); CPCOMMIT();
    load_bf(0, 0, bfA);

    #pragma unroll 1
    for (int kt = 0; kt < 9; kt++) {
        CPWAIT0();
        __syncthreads();                       // publish A(kt) (+zero rows at kt=0)
        if (kt < 8) { prefetch_A(kt + 1); CPCOMMIT(); }

        const uint32_t abase = sb + (kt & 1) * ABUF_SZ;

        #pragma unroll 1
        for (int tp = 0; tp < 9; tp++) {
            const int T = kt * 9 + tp;

            // shifted A row addresses for this tap (zero row 256 when invalid)
            const int dh = tp / 3 - 1, dw = tp % 3 - 1;
            const int sj = jlane + dw;
            const bool jv = (unsigned)sj < 16u;
            uint32_t rowbase[4];
            int key[4];
            bool mval[4];
            #pragma unroll
            for (int mt = 0; mt < 4; mt++) {
                int si = wid * 4 + mt + dh;          // single pixel row per fragment
                mval[mt] = ((unsigned)si < 16u);     // uniform across the warp
                int srow = (jv && mval[mt]) ? si * 16 + sj : 256;
                rowbase[mt] = abase + (uint32_t)srow * 128;
                key[mt] = srow & 7;
            }

            const int Tn = (T < 80) ? T + 1 : T;
            #pragma unroll
            for (int k16 = 0; k16 < 4; k16++) {
                // ping-pong: even k16 consumes bfA / prefetches bfB, odd vice versa
                uint2* cur = (k16 & 1) ? bfB : bfA;
                uint2* nxt = (k16 & 1) ? bfA : bfB;
                if (k16 < 3) load_bf(T, k16 + 1, nxt);
                else         load_bf(Tn, 0, nxt);

                const int kc = k16 * 2 + a_kc_lane;
                #pragma unroll
                for (int mt = 0; mt < 4; mt++) {
                    if (!mval[mt]) continue;          // whole fragment is zero row
                    uint32_t a[4];
                    ldsm_x4(a, rowbase[mt] + ((kc ^ key[mt]) << 4));
                    #pragma unroll
                    for (int nt = 0; nt < 8; nt++)
                        mma16816(d[mt][nt], a, (const uint32_t*)&cur[nt]);
                }
            }
        }
    }

    // ---- epilogue: fragments -> smem acc [256][72] -> coalesced global ----
    __syncthreads();
    float* accS = (float*)smem;
    #pragma unroll
    for (int mt = 0; mt < 4; mt++) {
        #pragma unroll
        for (int r = 0; r < 4; r++) {
            const int p = M0 + mt * 16 + (lane >> 2) + ((r >> 1) & 1) * 8;
            float* dst = accS + p * 72 + (lane & 3) * 2 + (r & 1);
            #pragma unroll
            for (int nt = 0; nt < 8; nt++)
                dst[nt * 8] = d[mt][nt][r];
        }
    }
    __syncthreads();
    {
        #pragma unroll
        for (int h = 0; h < 2; h++) {
            const int p = tid + h * 128;
            const size_t obase = ((size_t)(b * 64) * 256
                                  + (size_t)(t1 * 16 + (p >> 4))) * 256
                                 + t2 * 16 + (p & 15);
            const float* arow = accS + p * 72;
            #pragma unroll 8
            for (int co = 0; co < 64; co++)
                out[obase + (size_t)co * 65536] = arow[co];
        }
    }
}

extern "C" void kernel_launch(void* const* d_in, const int* in_sizes, int n_in,
                              void* d_out, int out_size) {
    const float* inp = (const float*)d_in[0];   // (8, 64, 256, 256) fp32
    const float* ker = (const float*)d_in[1];   // (9, 64, 64, 3, 3) fp32
    float* out = (float*)d_out;                 // (8, 64, 256, 256) fp32

    cudaFuncSetAttribute(prep_kernel,
                         cudaFuncAttributeMaxDynamicSharedMemorySize, 32768);
    dim3 grid(16, 16, 8);   // (u2/t2, u1/t1, b)
    prep_kernel<<<grid, 256, 32768>>>(inp, ker);

    cudaFuncSetAttribute(cocov_mma_kernel,
                         cudaFuncAttributeMaxDynamicSharedMemorySize, SM_TOTAL);
    cocov_mma_kernel<<<grid, 128, SM_TOTAL>>>(out);
}

// round 14
// speedup vs baseline: 1.1843x; 1.1843x over previous
#include <cuda_runtime.h>
#include <cuda_fp16.h>
#include <cstdint>

// ============================================================================
// CoCov via mma.sync (HMMA) fp16 single-pass, input-shift formulation.
// out[p] = sum_{kt 3x3} sum_{tap 3x3} X_kt[p + (dh-1,dw-1)] @ W[kt,tap]
// B in mma-fragment order in DRAM, per-warp __ldg with k16 register ping-pong
// (L1-resident). A pre-converted to swizzled fp16 panels (preproc kernel also
// rearranges W), cp.async double-buffered, ONE barrier per kt. Branch-free
// inner loop; all 4 A-ldsm of a k16 step hoisted ahead of the 32 MMAs.
// ============================================================================

// B in fragment order: [T=kt*9+tap][k16 4][nt 8][lane 32] uint2
__device__ uint2 g_bw2[81 * 1024];
// pre-converted A panels: [b*256 + u1*16 + u2][pix 256][128B swizzled row]
__device__ uint4 g_bA[2048 * 2048];

// one preprocessing kernel: every block does its A panel; first 324 blocks
// additionally rearrange the weights (81*1024 uint2 elements).
__global__ void __launch_bounds__(256) prep_kernel(const float* __restrict__ inp,
                                                   const float* __restrict__ K) {
    extern __shared__ char sm[];
    const int tid = threadIdx.x;
    const int u2 = blockIdx.x, u1 = blockIdx.y, b = blockIdx.z;
    const int bid = (b * 16 + u1) * 16 + u2;

    // ---- weight rearrange (blocks 0..323) ----
    {
        int gid = bid * 256 + tid;
        if (gid < 81 * 1024) {
            int lane = gid & 31;
            int nt   = (gid >> 5) & 7;
            int k16  = (gid >> 8) & 3;
            int T    = gid >> 10;
            int tp = T % 9, kt = T / 9;
            int co = nt * 8 + (lane >> 2);
            int k0 = k16 * 16 + (lane & 3) * 2;
            const float* Kc = K + ((kt * 64 + co) * 64) * 9 + tp;   // [k][co][ci][dh][dw]
            __half2 lo2(__float2half(Kc[(size_t)k0 * 9]),
                        __float2half(Kc[(size_t)(k0 + 1) * 9]));
            __half2 hi2(__float2half(Kc[(size_t)(k0 + 8) * 9]),
                        __float2half(Kc[(size_t)(k0 + 9) * 9]));
            g_bw2[gid] = make_uint2(*(uint32_t*)&lo2, *(uint32_t*)&hi2);
        }
    }

    // ---- A panel convert: fp32 -> fp16, swizzled 128B rows ----
    const float* src = inp + (size_t)b * 64 * 65536
                     + (size_t)(u1 * 16 + (tid >> 4)) * 256 + u2 * 16 + (tid & 15);
    const uint32_t rowa = tid * 128;
    #pragma unroll
    for (int ch = 0; ch < 8; ch++) {
        uint32_t hi4[4];
        #pragma unroll
        for (int e = 0; e < 4; e++) {
            float x0 = __ldg(src + (size_t)(ch * 8 + 2 * e) * 65536);
            float x1 = __ldg(src + (size_t)(ch * 8 + 2 * e + 1) * 65536);
            __half2 hp(__float2half(x0), __float2half(x1));
            hi4[e] = *(uint32_t*)&hp;
        }
        uint32_t off = rowa + ((ch ^ (tid & 7)) << 4);
        *(uint4*)(sm + off) = make_uint4(hi4[0], hi4[1], hi4[2], hi4[3]);
    }
    __syncthreads();
    uint4* dst = g_bA + (size_t)bid * 2048;
    const uint4* s4 = (const uint4*)sm;
    #pragma unroll
    for (int k = 0; k < 8; k++) dst[tid + k * 256] = s4[tid + k * 256];
}

__device__ __forceinline__ uint32_t smem_u32(const void* p) {
    uint32_t a;
    asm("{ .reg .u64 t; cvta.to.shared.u64 t, %1; cvt.u32.u64 %0, t; }" : "=r"(a) : "l"(p));
    return a;
}
__device__ __forceinline__ void ldsm_x4(uint32_t* r, uint32_t addr) {
    asm volatile("ldmatrix.sync.aligned.m8n8.x4.shared.b16 {%0,%1,%2,%3}, [%4];"
                 : "=r"(r[0]), "=r"(r[1]), "=r"(r[2]), "=r"(r[3]) : "r"(addr));
}
__device__ __forceinline__ void mma16816(float* d, const uint32_t* a, const uint32_t* b) {
    asm volatile(
        "mma.sync.aligned.m16n8k16.row.col.f32.f16.f16.f32 "
        "{%0,%1,%2,%3}, {%4,%5,%6,%7}, {%8,%9}, {%0,%1,%2,%3};"
        : "+f"(d[0]), "+f"(d[1]), "+f"(d[2]), "+f"(d[3])
        : "r"(a[0]), "r"(a[1]), "r"(a[2]), "r"(a[3]), "r"(b[0]), "r"(b[1]));
}

#define CP16(dst, src, sz) \
    asm volatile("cp.async.cg.shared.global [%0], [%1], 16, %2;" \
                 :: "r"(dst), "l"(src), "r"(sz) : "memory")
#define CPCOMMIT() asm volatile("cp.async.commit_group;" ::: "memory")
#define CPWAIT0()  asm volatile("cp.async.wait_group 0;" ::: "memory")

// smem: A bufs: 2 x [257 rows][128B] (row 256 = zeros) = 65792,
// epilogue reuses smem as acc [pix 256][72] fp32 = 73728  -> SM_TOTAL = 73728
#define ABUF_SZ  32896              // 257 * 128
#define SM_TOTAL 73728              // max(2*ABUF_SZ, 256*72*4); 2 CTAs/SM

__global__ void __launch_bounds__(128, 2)
cocov_mma_kernel(float* __restrict__ out) {
    extern __shared__ char smem[];
    const uint32_t sb = smem_u32(smem);

    const int tid = threadIdx.x;
    const int lane = tid & 31;
    const int wid = tid >> 5;              // 0..3, each warp: 64 pixels
    const int t2 = blockIdx.x, t1 = blockIdx.y, b = blockIdx.z;
    const int M0 = wid * 64;

    // zero rows (row 256 of each A buf), written once (published by kt=0 barrier)
    if (tid < 64) {
        int buf = tid >> 5;
        *(float*)(smem + buf * ABUF_SZ + 256 * 128 + (tid & 31) * 4) = 0.f;
    }

    auto prefetch_A = [&](int kt) {
        const int tt1 = t1 + kt / 3 - 1;
        const int tt2 = t2 + kt % 3 - 1;
        const bool v = ((unsigned)tt1 < 16u) && ((unsigned)tt2 < 16u);
        const uint4* srcp = g_bA + (size_t)(b * 256 + (v ? tt1 * 16 + tt2 : 0)) * 2048;
        const int sz = v ? 16 : 0;
        const uint32_t abase = sb + (kt & 1) * ABUF_SZ;
        #pragma unroll
        for (int it = 0; it < 16; it++) {
            int e = tid + it * 128;            // 0..2047
            CP16(abase + e * 16, (const char*)(srcp + e), sz);
        }
    };

    // B fragment loader: tap T, k-step k16 -> 8 uint2 (one per nt)
    const uint2* bbase_g = g_bw2 + lane;
    auto load_bf = [&](int T, int k16, uint2* bf) {
        const uint2* p = bbase_g + (size_t)T * 1024 + k16 * 256;
        #pragma unroll
        for (int nt = 0; nt < 8; nt++) bf[nt] = __ldg(p + nt * 32);
    };

    // ldmatrix lane addressing pieces
    const int a_kc_lane = (lane >> 4);
    const int jlane     = lane & 15;

    float d[4][8][4];
    #pragma unroll
    for (int mt = 0; mt < 4; mt++)
        #pragma unroll
        for (int nt = 0; nt < 8; nt++)
            #pragma unroll
            for (int r = 0; r < 4; r++) d[mt][nt][r] = 0.f;

    uint2 bfA[8], bfB[8];

    // prologue
    prefetch_A(0); CPCOMMIT();
    load_bf(0, 0, bfA);

    #pragma unroll 1
    for (int kt = 0; kt < 9; kt++) {
        CPWAIT0();
        __syncthreads();                       // publish A(kt) (+zero rows at kt=0)
        if (kt < 8) { prefetch_A(kt + 1); CPCOMMIT(); }

        const uint32_t abase = sb + (kt & 1) * ABUF_SZ;

        #pragma unroll 1
        for (int tp = 0; tp < 9; tp++) {
            const int T = kt * 9 + tp;

            // shifted A row addresses for this tap (zero row 256 when invalid)
            const int dh = tp / 3 - 1, dw = tp % 3 - 1;
            const int sj = jlane + dw;
            const bool jv = (unsigned)sj < 16u;
            uint32_t rowbase[4];
            int key[4];
            #pragma unroll
            for (int mt = 0; mt < 4; mt++) {
                int si = wid * 4 + mt + dh;
                int srow = (jv && ((unsigned)si < 16u)) ? si * 16 + sj : 256;
                rowbase[mt] = abase + (uint32_t)srow * 128;
                key[mt] = srow & 7;
            }

            const int Tn = (T < 80) ? T + 1 : T;
            #pragma unroll
            for (int k16 = 0; k16 < 4; k16++) {
                // ping-pong: even k16 consumes bfA / prefetches bfB, odd vice versa
                uint2* cur = (k16 & 1) ? bfB : bfA;
                uint2* nxt = (k16 & 1) ? bfA : bfB;
                if (k16 < 3) load_bf(T, k16 + 1, nxt);
                else         load_bf(Tn, 0, nxt);

                const int kc = k16 * 2 + a_kc_lane;
                // hoist ALL A-ldsm of this k16 ahead of the 32 MMAs
                uint32_t a[4][4];
                #pragma unroll
                for (int mt = 0; mt < 4; mt++)
                    ldsm_x4(a[mt], rowbase[mt] + ((kc ^ key[mt]) << 4));
                #pragma unroll
                for (int mt = 0; mt < 4; mt++)
                    #pragma unroll
                    for (int nt = 0; nt < 8; nt++)
                        mma16816(d[mt][nt], a[mt], (const uint32_t*)&cur[nt]);
            }
        }
    }

    // ---- epilogue: fragments -> smem acc [256][72] -> coalesced global ----
    __syncthreads();
    float* accS = (float*)smem;
    #pragma unroll
    for (int mt = 0; mt < 4; mt++) {
        #pragma unroll
        for (int r = 0; r < 4; r++) {
            const int p = M0 + mt * 16 + (lane >> 2) + ((r >> 1) & 1) * 8;
            float* dst = accS + p * 72 + (lane & 3) * 2 + (r & 1);
            #pragma unroll
            for (int nt = 0; nt < 8; nt++)
                dst[nt * 8] = d[mt][nt][r];
        }
    }
    __syncthreads();
    {
        #pragma unroll
        for (int h = 0; h < 2; h++) {
            const int p = tid + h * 128;
            const size_t obase = ((size_t)(b * 64) * 256
                                  + (size_t)(t1 * 16 + (p >> 4))) * 256
                                 + t2 * 16 + (p & 15);
            const float* arow = accS + p * 72;
            #pragma unroll 8
            for (int co = 0; co < 64; co++)
                out[obase + (size_t)co * 65536] = arow[co];
        }
    }
}

extern "C" void kernel_launch(void* const* d_in, const int* in_sizes, int n_in,
                              void* d_out, int out_size) {
    const float* inp = (const float*)d_in[0];   // (8, 64, 256, 256) fp32
    const float* ker = (const float*)d_in[1];   // (9, 64, 64, 3, 3) fp32
    float* out = (float*)d_out;                 // (8, 64, 256, 256) fp32

    cudaFuncSetAttribute(prep_kernel,
                         cudaFuncAttributeMaxDynamicSharedMemorySize, 32768);
    dim3 grid(16, 16, 8);   // (u2/t2, u1/t1, b)
    prep_kernel<<<grid, 256, 32768>>>(inp, ker);

    cudaFuncSetAttribute(cocov_mma_kernel,
                         cudaFuncAttributeMaxDynamicSharedMemorySize, SM_TOTAL);
    cocov_mma_kernel<<<grid, 128, SM_TOTAL>>>(out);
}

// round 15
// speedup vs baseline: 1.2624x; 1.0659x over previous
#include <cuda_runtime.h>
#include <cuda_fp16.h>
#include <cstdint>

// ============================================================================
// CoCov via mma.sync (HMMA) fp16 single-pass, input-shift formulation.
// out[p] = sum_{kt 3x3} sum_{tap 3x3} X_kt[p + (dh-1,dw-1)] @ W[kt,tap]
// B in mma-fragment order in DRAM, per-warp __ldg with k16 register ping-pong
// (L1-resident). A pre-converted to swizzled fp16 panels (preproc kernel also
// rearranges W), cp.async double-buffered, ONE barrier per kt. Branch-free
// inner loop with hoisted A-ldsm; block-uniform skip of all-zero kt panels.
// ============================================================================

// B in fragment order: [T=kt*9+tap][k16 4][nt 8][lane 32] uint2
__device__ uint2 g_bw2[81 * 1024];
// pre-converted A panels: [b*256 + u1*16 + u2][pix 256][128B swizzled row]
__device__ uint4 g_bA[2048 * 2048];

// one preprocessing kernel: every block does its A panel; first 324 blocks
// additionally rearrange the weights (81*1024 uint2 elements).
__global__ void __launch_bounds__(256) prep_kernel(const float* __restrict__ inp,
                                                   const float* __restrict__ K) {
    extern __shared__ char sm[];
    const int tid = threadIdx.x;
    const int u2 = blockIdx.x, u1 = blockIdx.y, b = blockIdx.z;
    const int bid = (b * 16 + u1) * 16 + u2;

    // ---- weight rearrange (blocks 0..323) ----
    {
        int gid = bid * 256 + tid;
        if (gid < 81 * 1024) {
            int lane = gid & 31;
            int nt   = (gid >> 5) & 7;
            int k16  = (gid >> 8) & 3;
            int T    = gid >> 10;
            int tp = T % 9, kt = T / 9;
            int co = nt * 8 + (lane >> 2);
            int k0 = k16 * 16 + (lane & 3) * 2;
            const float* Kc = K + ((kt * 64 + co) * 64) * 9 + tp;   // [k][co][ci][dh][dw]
            __half2 lo2(__float2half(Kc[(size_t)k0 * 9]),
                        __float2half(Kc[(size_t)(k0 + 1) * 9]));
            __half2 hi2(__float2half(Kc[(size_t)(k0 + 8) * 9]),
                        __float2half(Kc[(size_t)(k0 + 9) * 9]));
            g_bw2[gid] = make_uint2(*(uint32_t*)&lo2, *(uint32_t*)&hi2);
        }
    }

    // ---- A panel convert: fp32 -> fp16, swizzled 128B rows ----
    const float* src = inp + (size_t)b * 64 * 65536
                     + (size_t)(u1 * 16 + (tid >> 4)) * 256 + u2 * 16 + (tid & 15);
    const uint32_t rowa = tid * 128;
    #pragma unroll
    for (int ch = 0; ch < 8; ch++) {
        uint32_t hi4[4];
        #pragma unroll
        for (int e = 0; e < 4; e++) {
            float x0 = __ldg(src + (size_t)(ch * 8 + 2 * e) * 65536);
            float x1 = __ldg(src + (size_t)(ch * 8 + 2 * e + 1) * 65536);
            __half2 hp(__float2half(x0), __float2half(x1));
            hi4[e] = *(uint32_t*)&hp;
        }
        uint32_t off = rowa + ((ch ^ (tid & 7)) << 4);
        *(uint4*)(sm + off) = make_uint4(hi4[0], hi4[1], hi4[2], hi4[3]);
    }
    __syncthreads();
    uint4* dst = g_bA + (size_t)bid * 2048;
    const uint4* s4 = (const uint4*)sm;
    #pragma unroll
    for (int k = 0; k < 8; k++) dst[tid + k * 256] = s4[tid + k * 256];
}

__device__ __forceinline__ uint32_t smem_u32(const void* p) {
    uint32_t a;
    asm("{ .reg .u64 t; cvta.to.shared.u64 t, %1; cvt.u32.u64 %0, t; }" : "=r"(a) : "l"(p));
    return a;
}
__device__ __forceinline__ void ldsm_x4(uint32_t* r, uint32_t addr) {
    asm volatile("ldmatrix.sync.aligned.m8n8.x4.shared.b16 {%0,%1,%2,%3}, [%4];"
                 : "=r"(r[0]), "=r"(r[1]), "=r"(r[2]), "=r"(r[3]) : "r"(addr));
}
__device__ __forceinline__ void mma16816(float* d, const uint32_t* a, const uint32_t* b) {
    asm volatile(
        "mma.sync.aligned.m16n8k16.row.col.f32.f16.f16.f32 "
        "{%0,%1,%2,%3}, {%4,%5,%6,%7}, {%8,%9}, {%0,%1,%2,%3};"
        : "+f"(d[0]), "+f"(d[1]), "+f"(d[2]), "+f"(d[3])
        : "r"(a[0]), "r"(a[1]), "r"(a[2]), "r"(a[3]), "r"(b[0]), "r"(b[1]));
}

#define CP16(dst, src, sz) \
    asm volatile("cp.async.cg.shared.global [%0], [%1], 16, %2;" \
                 :: "r"(dst), "l"(src), "r"(sz) : "memory")
#define CPCOMMIT() asm volatile("cp.async.commit_group;" ::: "memory")
#define CPWAIT0()  asm volatile("cp.async.wait_group 0;" ::: "memory")

// smem: A bufs: 2 x [257 rows][128B] (row 256 = zeros) = 65792,
// epilogue reuses smem as acc [pix 256][72] fp32 = 73728  -> SM_TOTAL = 73728
#define ABUF_SZ  32896              // 257 * 128
#define SM_TOTAL 73728              // max(2*ABUF_SZ, 256*72*4); 2 CTAs/SM

__global__ void __launch_bounds__(128, 2)
cocov_mma_kernel(float* __restrict__ out) {
    extern __shared__ char smem[];
    const uint32_t sb = smem_u32(smem);

    const int tid = threadIdx.x;
    const int lane = tid & 31;
    const int wid = tid >> 5;              // 0..3, each warp: 64 pixels
    const int t2 = blockIdx.x, t1 = blockIdx.y, b = blockIdx.z;
    const int M0 = wid * 64;

    // zero rows (row 256 of each A buf), written once (published by kt=0 barrier)
    if (tid < 64) {
        int buf = tid >> 5;
        *(float*)(smem + buf * ABUF_SZ + 256 * 128 + (tid & 31) * 4) = 0.f;
    }

    auto kt_valid = [&](int kt) -> bool {
        const int tt1 = t1 + kt / 3 - 1;
        const int tt2 = t2 + kt % 3 - 1;
        return ((unsigned)tt1 < 16u) && ((unsigned)tt2 < 16u);
    };

    auto prefetch_A = [&](int kt) {
        const int tt1 = t1 + kt / 3 - 1;
        const int tt2 = t2 + kt % 3 - 1;
        const bool v = ((unsigned)tt1 < 16u) && ((unsigned)tt2 < 16u);
        const uint4* srcp = g_bA + (size_t)(b * 256 + (v ? tt1 * 16 + tt2 : 0)) * 2048;
        const int sz = v ? 16 : 0;
        const uint32_t abase = sb + (kt & 1) * ABUF_SZ;
        #pragma unroll
        for (int it = 0; it < 16; it++) {
            int e = tid + it * 128;            // 0..2047
            CP16(abase + e * 16, (const char*)(srcp + e), sz);
        }
    };

    // B fragment loader: tap T, k-step k16 -> 8 uint2 (one per nt)
    const uint2* bbase_g = g_bw2 + lane;
    auto load_bf = [&](int T, int k16, uint2* bf) {
        const uint2* p = bbase_g + (size_t)T * 1024 + k16 * 256;
        #pragma unroll
        for (int nt = 0; nt < 8; nt++) bf[nt] = __ldg(p + nt * 32);
    };

    // ldmatrix lane addressing pieces
    const int a_kc_lane = (lane >> 4);
    const int jlane     = lane & 15;

    float d[4][8][4];
    #pragma unroll
    for (int mt = 0; mt < 4; mt++)
        #pragma unroll
        for (int nt = 0; nt < 8; nt++)
            #pragma unroll
            for (int r = 0; r < 4; r++) d[mt][nt][r] = 0.f;

    uint2 bfA[8], bfB[8];

    // prologue
    prefetch_A(0); CPCOMMIT();
    load_bf(0, 0, bfA);

    #pragma unroll 1
    for (int kt = 0; kt < 9; kt++) {
        CPWAIT0();
        __syncthreads();                       // publish A(kt) (+zero rows at kt=0)
        if (kt < 8) { prefetch_A(kt + 1); CPCOMMIT(); }

        // block-uniform skip: whole neighbor tile out of grid -> panel is zero
        if (!kt_valid(kt)) {
            // re-seed B ping-pong chain for the next kt's first tap
            if (kt < 8) load_bf((kt + 1) * 9, 0, bfA);
            continue;
        }

        const uint32_t abase = sb + (kt & 1) * ABUF_SZ;

        #pragma unroll 1
        for (int tp = 0; tp < 9; tp++) {
            const int T = kt * 9 + tp;

            // shifted A row addresses for this tap (zero row 256 when invalid)
            const int dh = tp / 3 - 1, dw = tp % 3 - 1;
            const int sj = jlane + dw;
            const bool jv = (unsigned)sj < 16u;
            uint32_t rowbase[4];
            int key[4];
            #pragma unroll
            for (int mt = 0; mt < 4; mt++) {
                int si = wid * 4 + mt + dh;
                int srow = (jv && ((unsigned)si < 16u)) ? si * 16 + sj : 256;
                rowbase[mt] = abase + (uint32_t)srow * 128;
                key[mt] = srow & 7;
            }

            const int Tn = (T < 80) ? T + 1 : T;
            #pragma unroll
            for (int k16 = 0; k16 < 4; k16++) {
                // ping-pong: even k16 consumes bfA / prefetches bfB, odd vice versa
                uint2* cur = (k16 & 1) ? bfB : bfA;
                uint2* nxt = (k16 & 1) ? bfA : bfB;
                if (k16 < 3) load_bf(T, k16 + 1, nxt);
                else         load_bf(Tn, 0, nxt);

                const int kc = k16 * 2 + a_kc_lane;
                // hoist ALL A-ldsm of this k16 ahead of the 32 MMAs
                uint32_t a[4][4];
                #pragma unroll
                for (int mt = 0; mt < 4; mt++)
                    ldsm_x4(a[mt], rowbase[mt] + ((kc ^ key[mt]) << 4));
                #pragma unroll
                for (int mt = 0; mt < 4; mt++)
                    #pragma unroll
                    for (int nt = 0; nt < 8; nt++)
                        mma16816(d[mt][nt], a[mt], (const uint32_t*)&cur[nt]);
            }
        }
    }

    // ---- epilogue: fragments -> smem acc [256][72] -> coalesced global ----
    __syncthreads();
    float* accS = (float*)smem;
    #pragma unroll
    for (int mt = 0; mt < 4; mt++) {
        #pragma unroll
        for (int r = 0; r < 4; r++) {
            const int p = M0 + mt * 16 + (lane >> 2) + ((r >> 1) & 1) * 8;
            float* dst = accS + p * 72 + (lane & 3) * 2 + (r & 1);
            #pragma unroll
            for (int nt = 0; nt < 8; nt++)
                dst[nt * 8] = d[mt][nt][r];
        }
    }
    __syncthreads();
    {
        #pragma unroll
        for (int h = 0; h < 2; h++) {
            const int p = tid + h * 128;
            const size_t obase = ((size_t)(b * 64) * 256
                                  + (size_t)(t1 * 16 + (p >> 4))) * 256
                                 + t2 * 16 + (p & 15);
            const float* arow = accS + p * 72;
            #pragma unroll 8
            for (int co = 0; co < 64; co++)
                out[obase + (size_t)co * 65536] = arow[co];
        }
    }
}

extern "C" void kernel_launch(void* const* d_in, const int* in_sizes, int n_in,
                              void* d_out, int out_size) {
    const float* inp = (const float*)d_in[0];   // (8, 64, 256, 256) fp32
    const float* ker = (const float*)d_in[1];   // (9, 64, 64, 3, 3) fp32
    float* out = (float*)d_out;                 // (8, 64, 256, 256) fp32

    cudaFuncSetAttribute(prep_kernel,
                         cudaFuncAttributeMaxDynamicSharedMemorySize, 32768);
    dim3 grid(16, 16, 8);   // (u2/t2, u1/t1, b)
    prep_kernel<<<grid, 256, 32768>>>(inp, ker);

    cudaFuncSetAttribute(cocov_mma_kernel,
                         cudaFuncAttributeMaxDynamicSharedMemorySize, SM_TOTAL);
    cocov_mma_kernel<<<grid, 128, SM_TOTAL>>>(out);
}

// round 16
// speedup vs baseline: 1.3229x; 1.0480x over previous
#include <cuda_runtime.h>
#include <cuda_fp16.h>
#include <cstdint>

// ============================================================================
// CoCov via mma.sync (HMMA) fp16 single-pass, input-shift formulation.
// out[p] = sum_{kt 3x3} sum_{tap 3x3} X_kt[p + (dh-1,dw-1)] @ W[kt,tap]
// B in uint4-packed mma-fragment order in DRAM, per-warp __ldg with k16
// register ping-pong (L1-resident). A pre-converted to swizzled fp16 panels,
// cp.async double-buffered, ONE barrier per kt. Block-uniform zero-kt skip.
// Tap loop unrolled x3 for cross-tap ILP.
// ============================================================================

// B packed: [T=kt*9+tap][k16 4][np 4][lane 32] uint4
//   .xy = fragment uint2 for nt=2np, .zw = for nt=2np+1
//   (per nt: co = nt*8 + (lane>>2), k0 = k16*16 + (lane&3)*2;
//    uint2 = { half2(K[k0],K[k0+1]), half2(K[k0+8],K[k0+9]) })
__device__ uint4 g_bw4[81 * 512];
// pre-converted A panels: [b*256 + u1*16 + u2][pix 256][128B swizzled row]
__device__ uint4 g_bA[2048 * 2048];

// one preprocessing kernel: every block does its A panel; first blocks also
// rearrange the weights (81*512 = 41472 uint4 elements).
__global__ void __launch_bounds__(256) prep_kernel(const float* __restrict__ inp,
                                                   const float* __restrict__ K) {
    extern __shared__ char sm[];
    const int tid = threadIdx.x;
    const int u2 = blockIdx.x, u1 = blockIdx.y, b = blockIdx.z;
    const int bid = (b * 16 + u1) * 16 + u2;

    // ---- weight rearrange ----
    {
        int gid = bid * 256 + tid;
        if (gid < 81 * 512) {
            int lane = gid & 31;
            int np   = (gid >> 5) & 3;
            int k16  = (gid >> 7) & 3;
            int T    = gid >> 9;
            int tp = T % 9, kt = T / 9;
            int k0 = k16 * 16 + (lane & 3) * 2;
            uint32_t r[2];
            #pragma unroll
            for (int h = 0; h < 2; h++) {
                int co = (2 * np + h) * 8 + (lane >> 2);
                const float* Kc = K + ((kt * 64 + co) * 64) * 9 + tp; // [k][co][ci][9]
                __half2 lo2(__float2half(Kc[(size_t)k0 * 9]),
                            __float2half(Kc[(size_t)(k0 + 1) * 9]));
                __half2 hi2(__float2half(Kc[(size_t)(k0 + 8) * 9]),
                            __float2half(Kc[(size_t)(k0 + 9) * 9]));
                r[0] = *(uint32_t*)&lo2;
                r[1] = *(uint32_t*)&hi2;
                if (h == 0) { g_bw4[gid].x = r[0]; g_bw4[gid].y = r[1]; }
                else        { g_bw4[gid].z = r[0]; g_bw4[gid].w = r[1]; }
            }
        }
    }

    // ---- A panel convert: fp32 -> fp16, swizzled 128B rows ----
    const float* src = inp + (size_t)b * 64 * 65536
                     + (size_t)(u1 * 16 + (tid >> 4)) * 256 + u2 * 16 + (tid & 15);
    const uint32_t rowa = tid * 128;
    #pragma unroll
    for (int ch = 0; ch < 8; ch++) {
        uint32_t hi4[4];
        #pragma unroll
        for (int e = 0; e < 4; e++) {
            float x0 = __ldg(src + (size_t)(ch * 8 + 2 * e) * 65536);
            float x1 = __ldg(src + (size_t)(ch * 8 + 2 * e + 1) * 65536);
            __half2 hp(__float2half(x0), __float2half(x1));
            hi4[e] = *(uint32_t*)&hp;
        }
        uint32_t off = rowa + ((ch ^ (tid & 7)) << 4);
        *(uint4*)(sm + off) = make_uint4(hi4[0], hi4[1], hi4[2], hi4[3]);
    }
    __syncthreads();
    uint4* dst = g_bA + (size_t)bid * 2048;
    const uint4* s4 = (const uint4*)sm;
    #pragma unroll
    for (int k = 0; k < 8; k++) dst[tid + k * 256] = s4[tid + k * 256];
}

__device__ __forceinline__ uint32_t smem_u32(const void* p) {
    uint32_t a;
    asm("{ .reg .u64 t; cvta.to.shared.u64 t, %1; cvt.u32.u64 %0, t; }" : "=r"(a) : "l"(p));
    return a;
}
__device__ __forceinline__ void ldsm_x4(uint32_t* r, uint32_t addr) {
    asm volatile("ldmatrix.sync.aligned.m8n8.x4.shared.b16 {%0,%1,%2,%3}, [%4];"
                 : "=r"(r[0]), "=r"(r[1]), "=r"(r[2]), "=r"(r[3]) : "r"(addr));
}
__device__ __forceinline__ void mma16816(float* d, const uint32_t* a, const uint32_t* b) {
    asm volatile(
        "mma.sync.aligned.m16n8k16.row.col.f32.f16.f16.f32 "
        "{%0,%1,%2,%3}, {%4,%5,%6,%7}, {%8,%9}, {%0,%1,%2,%3};"
        : "+f"(d[0]), "+f"(d[1]), "+f"(d[2]), "+f"(d[3])
        : "r"(a[0]), "r"(a[1]), "r"(a[2]), "r"(a[3]), "r"(b[0]), "r"(b[1]));
}

#define CP16(dst, src, sz) \
    asm volatile("cp.async.cg.shared.global [%0], [%1], 16, %2;" \
                 :: "r"(dst), "l"(src), "r"(sz) : "memory")
#define CPCOMMIT() asm volatile("cp.async.commit_group;" ::: "memory")
#define CPWAIT0()  asm volatile("cp.async.wait_group 0;" ::: "memory")

// smem: A bufs: 2 x [257 rows][128B] (row 256 = zeros) = 65792,
// epilogue reuses smem as acc [pix 256][72] fp32 = 73728  -> SM_TOTAL = 73728
#define ABUF_SZ  32896              // 257 * 128
#define SM_TOTAL 73728              // max(2*ABUF_SZ, 256*72*4); 2 CTAs/SM

__global__ void __launch_bounds__(128, 2)
cocov_mma_kernel(float* __restrict__ out) {
    extern __shared__ char smem[];
    const uint32_t sb = smem_u32(smem);

    const int tid = threadIdx.x;
    const int lane = tid & 31;
    const int wid = tid >> 5;              // 0..3, each warp: 64 pixels
    const int t2 = blockIdx.x, t1 = blockIdx.y, b = blockIdx.z;
    const int M0 = wid * 64;

    // zero rows (row 256 of each A buf), written once (published by kt=0 barrier)
    if (tid < 64) {
        int buf = tid >> 5;
        *(float*)(smem + buf * ABUF_SZ + 256 * 128 + (tid & 31) * 4) = 0.f;
    }

    auto kt_valid = [&](int kt) -> bool {
        const int tt1 = t1 + kt / 3 - 1;
        const int tt2 = t2 + kt % 3 - 1;
        return ((unsigned)tt1 < 16u) && ((unsigned)tt2 < 16u);
    };

    auto prefetch_A = [&](int kt) {
        const int tt1 = t1 + kt / 3 - 1;
        const int tt2 = t2 + kt % 3 - 1;
        const bool v = ((unsigned)tt1 < 16u) && ((unsigned)tt2 < 16u);
        const uint4* srcp = g_bA + (size_t)(b * 256 + (v ? tt1 * 16 + tt2 : 0)) * 2048;
        const int sz = v ? 16 : 0;
        const uint32_t abase = sb + (kt & 1) * ABUF_SZ;
        #pragma unroll
        for (int it = 0; it < 16; it++) {
            int e = tid + it * 128;            // 0..2047
            CP16(abase + e * 16, (const char*)(srcp + e), sz);
        }
    };

    // B fragment loader: tap T, k-step k16 -> 4 uint4 (nt pairs)
    const uint4* bbase_g = g_bw4 + lane;
    auto load_bf = [&](int T, int k16, uint4* bf) {
        const uint4* p = bbase_g + (size_t)T * 512 + k16 * 128;
        #pragma unroll
        for (int np = 0; np < 4; np++) bf[np] = __ldg(p + np * 32);
    };

    // ldmatrix lane addressing pieces
    const int a_kc_lane = (lane >> 4);
    const int jlane     = lane & 15;

    float d[4][8][4];
    #pragma unroll
    for (int mt = 0; mt < 4; mt++)
        #pragma unroll
        for (int nt = 0; nt < 8; nt++)
            #pragma unroll
            for (int r = 0; r < 4; r++) d[mt][nt][r] = 0.f;

    uint4 bfA[4], bfB[4];

    // prologue
    prefetch_A(0); CPCOMMIT();
    load_bf(0, 0, bfA);

    #pragma unroll 1
    for (int kt = 0; kt < 9; kt++) {
        CPWAIT0();
        __syncthreads();                       // publish A(kt) (+zero rows at kt=0)
        if (kt < 8) { prefetch_A(kt + 1); CPCOMMIT(); }

        // block-uniform skip: whole neighbor tile out of grid -> panel is zero
        if (!kt_valid(kt)) {
            // re-seed B ping-pong chain for the next kt's first tap
            if (kt < 8) load_bf((kt + 1) * 9, 0, bfA);
            continue;
        }

        const uint32_t abase = sb + (kt & 1) * ABUF_SZ;

        #pragma unroll 3
        for (int tp = 0; tp < 9; tp++) {
            const int T = kt * 9 + tp;

            // shifted A row addresses for this tap (zero row 256 when invalid)
            const int dh = tp / 3 - 1, dw = tp % 3 - 1;
            const int sj = jlane + dw;
            const bool jv = (unsigned)sj < 16u;
            uint32_t rowbase[4];
            int key[4];
            #pragma unroll
            for (int mt = 0; mt < 4; mt++) {
                int si = wid * 4 + mt + dh;
                int srow = (jv && ((unsigned)si < 16u)) ? si * 16 + sj : 256;
                rowbase[mt] = abase + (uint32_t)srow * 128;
                key[mt] = srow & 7;
            }

            const int Tn = (T < 80) ? T + 1 : T;
            #pragma unroll
            for (int k16 = 0; k16 < 4; k16++) {
                // ping-pong: even k16 consumes bfA / prefetches bfB, odd vice versa
                uint4* cur = (k16 & 1) ? bfB : bfA;
                uint4* nxt = (k16 & 1) ? bfA : bfB;
                if (k16 < 3) load_bf(T, k16 + 1, nxt);
                else         load_bf(Tn, 0, nxt);

                const int kc = k16 * 2 + a_kc_lane;
                // hoist ALL A-ldsm of this k16 ahead of the 32 MMAs
                uint32_t a[4][4];
                #pragma unroll
                for (int mt = 0; mt < 4; mt++)
                    ldsm_x4(a[mt], rowbase[mt] + ((kc ^ key[mt]) << 4));
                #pragma unroll
                for (int mt = 0; mt < 4; mt++)
                    #pragma unroll
                    for (int nt = 0; nt < 8; nt++)
                        mma16816(d[mt][nt], a[mt],
                                 (const uint32_t*)&cur[nt >> 1] + ((nt & 1) << 1));
            }
        }
    }

    // ---- epilogue: fragments -> smem acc [256][72] -> coalesced global ----
    __syncthreads();
    float* accS = (float*)smem;
    #pragma unroll
    for (int mt = 0; mt < 4; mt++) {
        #pragma unroll
        for (int r = 0; r < 4; r++) {
            const int p = M0 + mt * 16 + (lane >> 2) + ((r >> 1) & 1) * 8;
            float* dst = accS + p * 72 + (lane & 3) * 2 + (r & 1);
            #pragma unroll
            for (int nt = 0; nt < 8; nt++)
                dst[nt * 8] = d[mt][nt][r];
        }
    }
    __syncthreads();
    {
        #pragma unroll
        for (int h = 0; h < 2; h++) {
            const int p = tid + h * 128;
            const size_t obase = ((size_t)(b * 64) * 256
                                  + (size_t)(t1 * 16 + (p >> 4))) * 256
                                 + t2 * 16 + (p & 15);
            const float* arow = accS + p * 72;
            #pragma unroll 8
            for (int co = 0; co < 64; co++)
                out[obase + (size_t)co * 65536] = arow[co];
        }
    }
}

extern "C" void kernel_launch(void* const* d_in, const int* in_sizes, int n_in,
                              void* d_out, int out_size) {
    const float* inp = (const float*)d_in[0];   // (8, 64, 256, 256) fp32
    const float* ker = (const float*)d_in[1];   // (9, 64, 64, 3, 3) fp32
    float* out = (float*)d_out;                 // (8, 64, 256, 256) fp32

    cudaFuncSetAttribute(prep_kernel,
                         cudaFuncAttributeMaxDynamicSharedMemorySize, 32768);
    dim3 grid(16, 16, 8);   // (u2/t2, u1/t1, b)
    prep_kernel<<<grid, 256, 32768>>>(inp, ker);

    cudaFuncSetAttribute(cocov_mma_kernel,
                         cudaFuncAttributeMaxDynamicSharedMemorySize, SM_TOTAL);
    cocov_mma_kernel<<<grid, 128, SM_TOTAL>>>(out);
}